// round 5
// baseline (speedup 1.0000x reference)
#include <cuda_runtime.h>
#include <cuda_bf16.h>
#include <cstdint>

#define NN   512
#define CZc  128
#define RTOT (NN*NN)

// ---------------------------------------------------------------------------
// Scratch (device globals).
// a/b bf16 hi/lo channel planes: [c][row] with per-plane matrix [i][k]/[j][k].
// g_upd fp32 planes [c][i][j]; g_g fp32 row-major [row][c].
// g_wh/g_wl: pre-converted weights, transposed [n][k] bf16 hi/lo.
// Weight order: 0=wga 1=wa 2=wgb 3=wb 4=wg 5=wout.
// ---------------------------------------------------------------------------
__device__ __nv_bfloat16 g_ah[(size_t)RTOT * CZc];
__device__ __nv_bfloat16 g_al[(size_t)RTOT * CZc];
__device__ __nv_bfloat16 g_bh[(size_t)RTOT * CZc];
__device__ __nv_bfloat16 g_bl[(size_t)RTOT * CZc];
__device__ float g_g  [(size_t)RTOT * CZc];
__device__ float g_upd[(size_t)RTOT * CZc];
__device__ __nv_bfloat16 g_wh[6 * 128 * 128];
__device__ __nv_bfloat16 g_wl[6 * 128 * 128];

// ---------------------------------------------------------------------------
// Helpers (baseline ISA only)
// ---------------------------------------------------------------------------
__device__ __forceinline__ uint32_t smem_u32(const void* p) {
    uint32_t a;
    asm("{ .reg .u64 t; cvta.to.shared.u64 t, %1; cvt.u32.u64 %0, t; }"
        : "=r"(a) : "l"(p));
    return a;
}
__device__ __forceinline__ float sigmoidf(float x) { return 1.0f / (1.0f + __expf(-x)); }

__device__ __forceinline__ void ldsm4(uint32_t* r, uint32_t addr) {
    asm volatile("ldmatrix.sync.aligned.m8n8.x4.shared.b16 {%0,%1,%2,%3}, [%4];"
                 : "=r"(r[0]), "=r"(r[1]), "=r"(r[2]), "=r"(r[3]) : "r"(addr));
}
__device__ __forceinline__ void mma_bf16(float* c, const uint32_t* a, const uint32_t* b) {
    asm volatile(
        "mma.sync.aligned.m16n8k16.row.col.f32.bf16.bf16.f32 "
        "{%0,%1,%2,%3}, {%4,%5,%6,%7}, {%8,%9}, {%0,%1,%2,%3};"
        : "+f"(c[0]), "+f"(c[1]), "+f"(c[2]), "+f"(c[3])
        : "r"(a[0]), "r"(a[1]), "r"(a[2]), "r"(a[3]), "r"(b[0]), "r"(b[1]));
}
__device__ __forceinline__ void cp16(uint32_t dst, const void* src) {
    asm volatile("cp.async.cg.shared.global [%0], [%1], 16;"
                 :: "r"(dst), "l"(src) : "memory");
}
#define CP_COMMIT() asm volatile("cp.async.commit_group;" ::: "memory")
#define CP_WAIT0()  asm volatile("cp.async.wait_group 0;"  ::: "memory")
#define CP_WAIT1()  asm volatile("cp.async.wait_group 1;"  ::: "memory")

// One K=32 chunk of 3-product hi/lo MMA.
// A tiles at ah/al (row stride astride bytes, column byte offset kcB..),
// B tiles at bh/bl (row stride 80 bytes, chunk-local columns).
__device__ __forceinline__ void chunk_mma(
    float (*acc)[8][4],
    uint32_t ah, uint32_t al, uint32_t bh, uint32_t bl,
    uint32_t astride, uint32_t kcB, int ib, int jb, int lane)
{
    const int lrow = lane & 15;
    const uint32_t lcolb = (uint32_t)((lane >> 4) & 1) * 16u;
    #pragma unroll
    for (int s = 0; s < 2; ++s) {
        const uint32_t colw = (uint32_t)s * 32u + lcolb;
        const uint32_t colz = kcB + colw;
        uint32_t Bh[4][4], Bl[4][4];
        #pragma unroll
        for (int p = 0; p < 4; ++p) {
            const uint32_t r = (uint32_t)(jb + p*16 + lrow);
            ldsm4(Bh[p], bh + r*80u + colw);
            ldsm4(Bl[p], bl + r*80u + colw);
        }
        #pragma unroll
        for (int m = 0; m < 2; ++m) {
            uint32_t Ah[4], Al[4];
            const uint32_t r = (uint32_t)(ib + m*16 + lrow);
            ldsm4(Ah, ah + r*astride + colz);
            ldsm4(Al, al + r*astride + colz);
            #pragma unroll
            for (int q = 0; q < 8; ++q) {
                const int p = q >> 1, o = q & 1;
                uint32_t vh[2] = { Bh[p][o], Bh[p][o + 2] };
                uint32_t vl[2] = { Bl[p][o], Bl[p][o + 2] };
                mma_bf16(acc[m][q], Ah, vh);
                mma_bf16(acc[m][q], Ah, vl);
                mma_bf16(acc[m][q], Al, vh);
            }
        }
    }
}

// Full K=128 (A and B both 272-byte row stride) — used by k_out.
__device__ __forceinline__ void mma_tile_k128(
    float (*acc)[8][4],
    uint32_t a_h, uint32_t a_l, uint32_t b_h, uint32_t b_l,
    int ib, int jb, int lane)
{
    const int lrow = lane & 15;
    const uint32_t lcolb = (uint32_t)((lane >> 4) & 1) * 16u;
    #pragma unroll
    for (int m = 0; m < 2; ++m)
        #pragma unroll
        for (int q = 0; q < 8; ++q)
            #pragma unroll
            for (int e = 0; e < 4; ++e) acc[m][q][e] = 0.f;
    #pragma unroll
    for (int s = 0; s < 8; ++s) {
        const uint32_t colb = (uint32_t)s * 32u + lcolb;
        uint32_t Bh[4][4], Bl[4][4];
        #pragma unroll
        for (int p = 0; p < 4; ++p) {
            const uint32_t r = (uint32_t)(jb + p*16 + lrow);
            ldsm4(Bh[p], b_h + r*272u + colb);
            ldsm4(Bl[p], b_l + r*272u + colb);
        }
        #pragma unroll
        for (int m = 0; m < 2; ++m) {
            uint32_t Ah[4], Al[4];
            const uint32_t r = (uint32_t)(ib + m*16 + lrow);
            ldsm4(Ah, a_h + r*272u + colb);
            ldsm4(Al, a_l + r*272u + colb);
            #pragma unroll
            for (int q = 0; q < 8; ++q) {
                const int p = q >> 1, o = q & 1;
                uint32_t vh[2] = { Bh[p][o], Bh[p][o + 2] };
                uint32_t vl[2] = { Bl[p][o], Bl[p][o + 2] };
                mma_bf16(acc[m][q], Ah, vh);
                mma_bf16(acc[m][q], Ah, vl);
                mma_bf16(acc[m][q], Al, vh);
            }
        }
    }
}

// ---------------------------------------------------------------------------
// Kernel 0: pre-convert weights to transposed [n][k] bf16 hi/lo planes.
// ---------------------------------------------------------------------------
__global__ void k_prep(const float* __restrict__ w0, const float* __restrict__ w1,
                       const float* __restrict__ w2, const float* __restrict__ w3,
                       const float* __restrict__ w4, const float* __restrict__ w5)
{
    const float* tbl[6] = { w0, w1, w2, w3, w4, w5 };
    const float* W = tbl[blockIdx.x];
    __nv_bfloat16* oh = g_wh + blockIdx.x * 16384;
    __nv_bfloat16* ol = g_wl + blockIdx.x * 16384;
    for (int idx = threadIdx.x; idx < 16384; idx += 256) {
        const int n = idx >> 7, k = idx & 127;
        const float v = W[k * 128 + n];
        const __nv_bfloat16 h = __float2bfloat16_rn(v);
        oh[idx] = h;
        ol[idx] = __float2bfloat16_rn(v - __bfloat162float(h));
    }
}

// ---------------------------------------------------------------------------
// Kernel 1: LN1 + 5 projections. z resident in smem; weights streamed as
// 20 K=32 chunks, double-buffered cp.async with 1-chunk lookahead.
// smem: zh@0 zl@34816 (272B rows) | wchunks@69632 (2 x 20480) | stage@110592.
// ---------------------------------------------------------------------------
__global__ __launch_bounds__(256, 1) void k_proj(
    const float* __restrict__ x,
    const float* __restrict__ gamma,
    const float* __restrict__ beta)
{
    extern __shared__ char sraw[];
    __nv_bfloat16* zh = (__nv_bfloat16*)sraw;                  // [128][136]
    __nv_bfloat16* zl = (__nv_bfloat16*)(sraw + 34816);
    float*         xs = (float*)(sraw + 110592);               // [128][136]
    __nv_bfloat16* stH = (__nv_bfloat16*)(sraw + 110592);      // [c][136]
    __nv_bfloat16* stL = (__nv_bfloat16*)(sraw + 110592 + 34816);

    const uint32_t sb  = smem_u32(sraw);
    const uint32_t zhb = sb, zlb = sb + 34816, wbB = sb + 69632;

    const int tid  = threadIdx.x;
    const int lane = tid & 31, wid = tid >> 5;
    const int r0   = blockIdx.x * 128;

    // prefetch first weight chunk immediately
    {
        const __nv_bfloat16* sH = g_wh;
        const __nv_bfloat16* sL = g_wl;
        #pragma unroll
        for (int t = 0; t < 2; ++t) {
            const int idx = t*256 + tid;
            const int row = idx >> 2, seg = idx & 3;
            cp16(wbB + (uint32_t)(row*80 + seg*16), sH + row*128 + seg*8);
            cp16(wbB + 10240u + (uint32_t)(row*80 + seg*16), sL + row*128 + seg*8);
        }
        CP_COMMIT();
    }

    // load x tile
    #pragma unroll
    for (int e = 0; e < 16; ++e) {
        const int idx = e * 256 + tid;
        const int r = idx >> 5, c4 = (idx & 31) * 4;
        *(float4*)&xs[r * 136 + c4] = *(const float4*)(x + (size_t)(r0 + r) * CZc + c4);
    }
    __syncthreads();

    // LN: warp handles 16 rows, write z hi/lo
    {
        const float ga0 = gamma[lane],      ga1 = gamma[lane + 32];
        const float ga2 = gamma[lane + 64], ga3 = gamma[lane + 96];
        const float be0 = beta[lane],       be1 = beta[lane + 32];
        const float be2 = beta[lane + 64],  be3 = beta[lane + 96];
        for (int rr = 0; rr < 16; ++rr) {
            const int r = wid * 16 + rr;
            const float v0 = xs[r*136 + lane];
            const float v1 = xs[r*136 + lane + 32];
            const float v2 = xs[r*136 + lane + 64];
            const float v3 = xs[r*136 + lane + 96];
            float s  = v0 + v1 + v2 + v3;
            float s2 = v0*v0 + v1*v1 + v2*v2 + v3*v3;
            #pragma unroll
            for (int o = 16; o; o >>= 1) {
                s  += __shfl_xor_sync(0xffffffffu, s,  o);
                s2 += __shfl_xor_sync(0xffffffffu, s2, o);
            }
            const float mu   = s * (1.0f / CZc);
            const float var  = s2 * (1.0f / CZc) - mu * mu;
            const float rstd = rsqrtf(var + 1e-5f);
            const float z0 = (v0-mu)*rstd*ga0 + be0;
            const float z1 = (v1-mu)*rstd*ga1 + be1;
            const float z2 = (v2-mu)*rstd*ga2 + be2;
            const float z3 = (v3-mu)*rstd*ga3 + be3;
            #pragma unroll
            for (int j = 0; j < 4; ++j) {
                const float zv = j==0?z0:j==1?z1:j==2?z2:z3;
                const int c = lane + j*32;
                const __nv_bfloat16 h = __float2bfloat16_rn(zv);
                zh[r*136 + c] = h;
                zl[r*136 + c] = __float2bfloat16_rn(zv - __bfloat162float(h));
            }
        }
    }

    const int wi_ = wid & 3, wj_ = wid >> 2;
    const int ib = wi_ * 32, jb = wj_ * 64;
    const int g = lane >> 2, tg = lane & 3;

    float accG[2][8][4], accL[2][8][4];

    for (int w = 0; w < 5; ++w) {
        float (*acc)[8][4] = (w == 1 || w == 3) ? accL : accG;
        #pragma unroll
        for (int m = 0; m < 2; ++m)
            #pragma unroll
            for (int q = 0; q < 8; ++q)
                #pragma unroll
                for (int e = 0; e < 4; ++e) acc[m][q][e] = 0.f;

        for (int kc = 0; kc < 4; ++kc) {
            const int gi = w * 4 + kc;
            if (gi + 1 < 20) {
                const int w2 = (gi+1) >> 2, kc2 = (gi+1) & 3;
                const __nv_bfloat16* sH = g_wh + w2*16384 + kc2*32;
                const __nv_bfloat16* sL = g_wl + w2*16384 + kc2*32;
                const uint32_t dst = wbB + (uint32_t)((gi+1) & 1) * 20480u;
                #pragma unroll
                for (int t = 0; t < 2; ++t) {
                    const int idx = t*256 + tid;
                    const int row = idx >> 2, seg = idx & 3;
                    cp16(dst + (uint32_t)(row*80 + seg*16), sH + row*128 + seg*8);
                    cp16(dst + 10240u + (uint32_t)(row*80 + seg*16), sL + row*128 + seg*8);
                }
                CP_COMMIT();
                CP_WAIT1();
            } else {
                CP_WAIT0();
            }
            __syncthreads();
            const uint32_t bb = wbB + (uint32_t)(gi & 1) * 20480u;
            chunk_mma(acc, zhb, zlb, bb, bb + 10240u, 272u, (uint32_t)(kc*64), ib, jb, lane);
            __syncthreads();
        }

        if (w == 1 || w == 3) {
            __nv_bfloat16* outh = (w == 1) ? g_ah : g_bh;
            __nv_bfloat16* outl = (w == 1) ? g_al : g_bl;
            // combine + stage transposed [c][i]
            #pragma unroll
            for (int m = 0; m < 2; ++m)
                #pragma unroll
                for (int q = 0; q < 8; ++q) {
                    const int cbase = jb + q*8 + tg*2;
                    const int ibase = ib + m*16 + g;
                    #pragma unroll
                    for (int e = 0; e < 4; ++e) {
                        const int c  = cbase + (e & 1);
                        const int ii = ibase + 8 * (e >> 1);
                        const float v = sigmoidf(accG[m][q][e]) * accL[m][q][e];
                        const __nv_bfloat16 h = __float2bfloat16_rn(v);
                        stH[c*136 + ii] = h;
                        stL[c*136 + ii] = __float2bfloat16_rn(v - __bfloat162float(h));
                    }
                }
            __syncthreads();
            {
                const int c = tid >> 1, half = tid & 1;
                __nv_bfloat16* dh = outh + (size_t)c * RTOT + r0 + half*64;
                __nv_bfloat16* dl = outl + (size_t)c * RTOT + r0 + half*64;
                #pragma unroll
                for (int bq = 0; bq < 8; ++bq) {
                    *(uint4*)(dh + bq*8) = *(const uint4*)&stH[c*136 + half*64 + bq*8];
                    *(uint4*)(dl + bq*8) = *(const uint4*)&stL[c*136 + half*64 + bq*8];
                }
            }
            __syncthreads();
        } else if (w == 4) {
            #pragma unroll
            for (int m = 0; m < 2; ++m)
                #pragma unroll
                for (int q = 0; q < 8; ++q) {
                    const int cc = jb + q*8 + tg*2;
                    const size_t i1 = (size_t)(r0 + ib + m*16 + g);
                    float2 v0, v1;
                    v0.x = sigmoidf(accG[m][q][0]); v0.y = sigmoidf(accG[m][q][1]);
                    v1.x = sigmoidf(accG[m][q][2]); v1.y = sigmoidf(accG[m][q][3]);
                    *(float2*)(g_g + i1*CZc + cc)       = v0;
                    *(float2*)(g_g + (i1 + 8)*CZc + cc) = v1;
                }
        }
    }
}

// ---------------------------------------------------------------------------
// Kernel 2: triangle einsum. K=32 chunks, double-buffered cp.async, occ 2.
// Per buffer: [Ah|Al|Bh|Bl][128][40 halves] = 40960 B; two buffers.
// ---------------------------------------------------------------------------
__global__ __launch_bounds__(256, 2) void k_tri()
{
    extern __shared__ char sraw[];
    const uint32_t sb = smem_u32(sraw);

    const int tid  = threadIdx.x;
    const int lane = tid & 31, wid = tid >> 5;
    const int c  = blockIdx.z;
    const int i0 = blockIdx.y * 128;
    const int j0 = blockIdx.x * 128;
    const int wi = wid & 3, wj = wid >> 2;
    const int ib = wi * 32, jb = wj * 64;

    const __nv_bfloat16* bases[4] = {
        g_ah + (size_t)c * RTOT + (size_t)i0 * NN,
        g_al + (size_t)c * RTOT + (size_t)i0 * NN,
        g_bh + (size_t)c * RTOT + (size_t)j0 * NN,
        g_bl + (size_t)c * RTOT + (size_t)j0 * NN };

    float acc[2][8][4];
    #pragma unroll
    for (int m = 0; m < 2; ++m)
        #pragma unroll
        for (int q = 0; q < 8; ++q)
            #pragma unroll
            for (int e = 0; e < 4; ++e) acc[m][q][e] = 0.f;

    // prefetch chunk 0
    {
        #pragma unroll
        for (int arr = 0; arr < 4; ++arr)
            #pragma unroll
            for (int t = 0; t < 2; ++t) {
                const int idx = t*256 + tid;
                const int row = idx >> 2, seg = idx & 3;
                cp16(sb + (uint32_t)(arr*10240 + row*80 + seg*16),
                     bases[arr] + (size_t)row * NN + seg*8);
            }
        CP_COMMIT();
    }

    for (int ch = 0; ch < 16; ++ch) {
        if (ch < 15) {
            const int k0 = (ch + 1) * 32;
            const uint32_t dst = sb + (uint32_t)((ch + 1) & 1) * 40960u;
            #pragma unroll
            for (int arr = 0; arr < 4; ++arr)
                #pragma unroll
                for (int t = 0; t < 2; ++t) {
                    const int idx = t*256 + tid;
                    const int row = idx >> 2, seg = idx & 3;
                    cp16(dst + (uint32_t)(arr*10240 + row*80 + seg*16),
                         bases[arr] + (size_t)row * NN + k0 + seg*8);
                }
            CP_COMMIT();
            CP_WAIT1();
        } else {
            CP_WAIT0();
        }
        __syncthreads();
        const uint32_t bb = sb + (uint32_t)(ch & 1) * 40960u;
        chunk_mma(acc, bb, bb + 10240u, bb + 20480u, bb + 30720u,
                  80u, 0u, ib, jb, lane);
        __syncthreads();
    }

    // epilogue -> g_upd fp32 plane
    {
        const int g = lane >> 2, tg = lane & 3;
        float* plane = g_upd + (size_t)c * RTOT;
        #pragma unroll
        for (int m = 0; m < 2; ++m) {
            const int irow = i0 + ib + m*16 + g;
            #pragma unroll
            for (int q = 0; q < 8; ++q) {
                const int jcol = j0 + jb + q*8 + tg*2;
                float2 v0; v0.x = acc[m][q][0]; v0.y = acc[m][q][1];
                float2 v1; v1.x = acc[m][q][2]; v1.y = acc[m][q][3];
                *(float2*)(plane + (size_t)irow       * NN + jcol) = v0;
                *(float2*)(plane + (size_t)(irow + 8) * NN + jcol) = v1;
            }
        }
    }
}

// ---------------------------------------------------------------------------
// Kernel 3: LN2(upd) @ w_out * gate -> out.
// wout prefetched at kernel entry (overlaps tile load + LN).
// smem: zh@0 zl@34816 | us@69632 (float [c][136]) | wh@139264 wl@174080.
// ---------------------------------------------------------------------------
__global__ __launch_bounds__(256, 1) void k_out(
    const float* __restrict__ gamma2,
    const float* __restrict__ beta2,
    float* __restrict__ out)
{
    extern __shared__ char sraw[];
    __nv_bfloat16* zh = (__nv_bfloat16*)sraw;
    __nv_bfloat16* zl = (__nv_bfloat16*)(sraw + 34816);
    float*         us = (float*)(sraw + 69632);
    const uint32_t sb  = smem_u32(sraw);
    const uint32_t whb = sb + 139264u, wlb = sb + 174080u;
    __shared__ float sgb[256];

    const int tid  = threadIdx.x;
    const int lane = tid & 31;
    const int r0   = blockIdx.x * 128;

    // prefetch wout hi/lo (pre-transposed [n][k])
    {
        const __nv_bfloat16* sH = g_wh + 5*16384;
        const __nv_bfloat16* sL = g_wl + 5*16384;
        #pragma unroll
        for (int t = 0; t < 8; ++t) {
            const int idx = t*256 + tid;
            const int row = idx >> 4, seg = idx & 15;
            cp16(whb + (uint32_t)(row*272 + seg*16), sH + row*128 + seg*8);
            cp16(wlb + (uint32_t)(row*272 + seg*16), sL + row*128 + seg*8);
        }
        CP_COMMIT();
    }

    if (tid < 128) sgb[tid] = gamma2[tid];
    else           sgb[tid] = beta2[tid - 128];

    // load upd tile from planes
    #pragma unroll
    for (int e = 0; e < 16; ++e) {
        const int idx = e * 256 + tid;
        const int cc = idx >> 5, r4 = (idx & 31) * 4;
        *(float4*)&us[cc * 136 + r4] =
            *(const float4*)(g_upd + (size_t)cc * RTOT + r0 + r4);
    }
    __syncthreads();

    // LN over c per row (2 threads per row), write z2 hi/lo
    {
        const int r = tid >> 1, h = tid & 1;
        float s = 0.f, s2 = 0.f;
        #pragma unroll 8
        for (int ccq = 0; ccq < 64; ++ccq) {
            const float v = us[(h*64 + ccq) * 136 + r];
            s += v; s2 += v * v;
        }
        s  += __shfl_xor_sync(0xffffffffu, s,  1);
        s2 += __shfl_xor_sync(0xffffffffu, s2, 1);
        const float mu   = s * (1.0f / CZc);
        const float var  = s2 * (1.0f / CZc) - mu * mu;
        const float rstd = rsqrtf(var + 1e-5f);
        #pragma unroll 8
        for (int ccq = 0; ccq < 64; ++ccq) {
            const int c = h*64 + ccq;
            const float v = us[c * 136 + r];
            const float z = (v - mu) * rstd * sgb[c] + sgb[128 + c];
            const __nv_bfloat16 hh = __float2bfloat16_rn(z);
            zh[r*136 + c] = hh;
            zl[r*136 + c] = __float2bfloat16_rn(z - __bfloat162float(hh));
        }
    }
    CP_WAIT0();
    __syncthreads();

    const int wid = tid >> 5;
    const int wi = wid & 3, wj = wid >> 2;
    const int ib = wi * 32, jb = wj * 64;
    float acc[2][8][4];
    mma_tile_k128(acc, sb, sb + 34816u, whb, wlb, ib, jb, lane);

    {
        const int g = lane >> 2, tg = lane & 3;
        #pragma unroll
        for (int m = 0; m < 2; ++m)
            #pragma unroll
            for (int q = 0; q < 8; ++q) {
                const int cc = jb + q*8 + tg*2;
                const size_t i1 = (size_t)(r0 + ib + m*16 + g);
                const float2 gg0 = *(const float2*)(g_g + i1*CZc + cc);
                const float2 gg1 = *(const float2*)(g_g + (i1 + 8)*CZc + cc);
                float2 v0, v1;
                v0.x = gg0.x * acc[m][q][0]; v0.y = gg0.y * acc[m][q][1];
                v1.x = gg1.x * acc[m][q][2]; v1.y = gg1.y * acc[m][q][3];
                *(float2*)(out + i1*CZc + cc)       = v0;
                *(float2*)(out + (i1 + 8)*CZc + cc) = v1;
            }
    }
}

// ---------------------------------------------------------------------------
// Launch
// ---------------------------------------------------------------------------
extern "C" void kernel_launch(void* const* d_in, const int* in_sizes, int n_in,
                              void* d_out, int out_size)
{
    const float* x    = (const float*)d_in[0];
    const float* g1   = (const float*)d_in[1];
    const float* b1   = (const float*)d_in[2];
    const float* wga  = (const float*)d_in[3];
    const float* wgb  = (const float*)d_in[4];
    const float* wa   = (const float*)d_in[5];
    const float* wb   = (const float*)d_in[6];
    const float* g2   = (const float*)d_in[7];
    const float* b2   = (const float*)d_in[8];
    const float* wout = (const float*)d_in[9];
    const float* wg   = (const float*)d_in[10];

    cudaFuncSetAttribute(k_proj, cudaFuncAttributeMaxDynamicSharedMemorySize, 180224);
    cudaFuncSetAttribute(k_tri,  cudaFuncAttributeMaxDynamicSharedMemorySize, 81920);
    cudaFuncSetAttribute(k_out,  cudaFuncAttributeMaxDynamicSharedMemorySize, 208896);

    k_prep<<<6, 256>>>(wga, wa, wgb, wb, wg, wout);

    k_proj<<<RTOT / 128, 256, 180224>>>(x, g1, b1);

    dim3 grid(NN / 128, NN / 128, CZc);
    k_tri<<<grid, 256, 81920>>>();

    k_out<<<RTOT / 128, 256, 208896>>>(g2, b2, (float*)d_out);
}